// round 8
// baseline (speedup 1.0000x reference)
#include <cuda_runtime.h>
#include <cuda_fp16.h>
#include <cstdint>
#include <cstddef>

#define EMBED    1024
#define NHEADS   16
#define HDIM     64
#define WSIZE    256
#define NWIN     64
#define MTOT     (NWIN*WSIZE)     /* 16384 */
#define LTOT     (MTOT-1)         /* 16383 */
#define QKVN     (3*EMBED)        /* 3072  */

// Scratch (allocation-free rule: __device__ globals)
__device__ float g_qkv[(size_t)MTOT * QKVN];   // gathered-order qkv, [M][3][16][64]
__device__ float g_osc[(size_t)MTOT * EMBED];  // scattered attention output

__device__ __forceinline__ float ex2f(float x) {
    float y;
    asm("ex2.approx.f32 %0, %1;" : "=f"(y) : "f"(x));
    return y;
}
__device__ __forceinline__ uint32_t packh2(float lo, float hi) {
    __half2 h = __floats2half2_rn(lo, hi);
    return *reinterpret_cast<uint32_t*>(&h);
}
__device__ __forceinline__ void mma_f16(float* c, const uint32_t* a, const uint32_t* b) {
    asm volatile(
        "mma.sync.aligned.m16n8k16.row.col.f32.f16.f16.f32 "
        "{%0,%1,%2,%3}, {%4,%5,%6,%7}, {%8,%9}, {%0,%1,%2,%3};"
        : "+f"(c[0]), "+f"(c[1]), "+f"(c[2]), "+f"(c[3])
        : "r"(a[0]), "r"(a[1]), "r"(a[2]), "r"(a[3]), "r"(b[0]), "r"(b[1]));
}
__device__ __forceinline__ void ldsm_x4(uint32_t* r, uint32_t addr) {
    asm volatile("ldmatrix.sync.aligned.m8n8.x4.shared.b16 {%0,%1,%2,%3}, [%4];"
                 : "=r"(r[0]), "=r"(r[1]), "=r"(r[2]), "=r"(r[3]) : "r"(addr));
}
__device__ __forceinline__ void ldsm_x4_t(uint32_t* r, uint32_t addr) {
    asm volatile("ldmatrix.sync.aligned.m8n8.x4.trans.shared.b16 {%0,%1,%2,%3}, [%4];"
                 : "=r"(r[0]), "=r"(r[1]), "=r"(r[2]), "=r"(r[3]) : "r"(addr));
}
__device__ __forceinline__ uint32_t smem_u32(const void* p) {
    uint32_t a;
    asm("{ .reg .u64 t; cvta.to.shared.u64 t, %1; cvt.u32.u64 %0, t; }"
        : "=r"(a) : "l"(p));
    return a;
}

// ---------------------------------------------------------------------------
// fp16 tensor-core GEMM (fp32 accum):
//   C[m][n] = sum_k A[row(m)][k] * B[n][k] + bias[n]
//   BM=BN=128, BK=32, 256 threads (8 warps, 4x2), warp tile 32x64,
//   mma.m16n8k16, smem tiles 128x40 halves (stride-40 conflict-free).
// ---------------------------------------------------------------------------
#define GSTR    40                 /* halves per smem row  */
#define GTILE_H (128 * GSTR)       /* 5120 halves per tile */
#define GTILE_B (GTILE_H * 2)      /* 10240 bytes          */

__global__ void __launch_bounds__(256, 2)
h16_gemm_kernel(const float* __restrict__ A,
                const float* __restrict__ B,
                const float* __restrict__ bias,
                float* __restrict__ C,
                const int* __restrict__ gidx,
                int Mrows, int N, int K, int Avalid)
{
    extern __shared__ __half smh[];
    __half* As = smh;                  // [2][128][40]
    __half* Bs = smh + 2 * GTILE_H;    // [2][128][40]
    __shared__ int arow[128];

    const int tid  = threadIdx.x;
    const int lane = tid & 31;
    const int wid  = tid >> 5;
    const int wm   = wid & 3;
    const int wn   = wid >> 2;
    const int bm   = blockIdx.y * 128;
    const int bn   = blockIdx.x * 128;

    if (tid < 128) {
        int m = bm + tid;
        int r = -1;
        if (m < Mrows) {
            r = gidx ? gidx[m] : m;
            if (r >= Avalid) r = -1;
        }
        arow[tid] = r;
    }
    __syncthreads();

    // copy mapping: row = tid&127, col half = (tid>>7)*16 .. +15 (16 floats)
    const int crow = tid & 127;
    const int ccol = (tid >> 7) << 4;
    const int ar   = arow[crow];

    float4 ra[4], rb[4];

    auto load_regs = [&](int k0) {
        const float* arp = (ar >= 0) ? &A[(size_t)ar * K + k0 + ccol] : nullptr;
        const float* brp = &B[(size_t)(bn + crow) * K + k0 + ccol];
        #pragma unroll
        for (int j = 0; j < 4; j++) {
            ra[j] = arp ? *reinterpret_cast<const float4*>(arp + 4 * j)
                        : make_float4(0.f, 0.f, 0.f, 0.f);
            rb[j] = *reinterpret_cast<const float4*>(brp + 4 * j);
        }
    };

    auto store_tile = [&](int buf) {
        __half* ap = As + buf * GTILE_H + crow * GSTR + ccol;
        __half* bp = Bs + buf * GTILE_H + crow * GSTR + ccol;
        uint4 u;
        u.x = packh2(ra[0].x, ra[0].y); u.y = packh2(ra[0].z, ra[0].w);
        u.z = packh2(ra[1].x, ra[1].y); u.w = packh2(ra[1].z, ra[1].w);
        *reinterpret_cast<uint4*>(ap) = u;
        u.x = packh2(ra[2].x, ra[2].y); u.y = packh2(ra[2].z, ra[2].w);
        u.z = packh2(ra[3].x, ra[3].y); u.w = packh2(ra[3].z, ra[3].w);
        *reinterpret_cast<uint4*>(ap + 8) = u;
        u.x = packh2(rb[0].x, rb[0].y); u.y = packh2(rb[0].z, rb[0].w);
        u.z = packh2(rb[1].x, rb[1].y); u.w = packh2(rb[1].z, rb[1].w);
        *reinterpret_cast<uint4*>(bp) = u;
        u.x = packh2(rb[2].x, rb[2].y); u.y = packh2(rb[2].z, rb[2].w);
        u.z = packh2(rb[3].x, rb[3].y); u.w = packh2(rb[3].z, rb[3].w);
        *reinterpret_cast<uint4*>(bp + 8) = u;
    };

    float acc[2][8][4];
    #pragma unroll
    for (int mt = 0; mt < 2; mt++)
        #pragma unroll
        for (int nt = 0; nt < 8; nt++)
            #pragma unroll
            for (int i = 0; i < 4; i++) acc[mt][nt][i] = 0.f;

    const int g4 = lane >> 2;
    const int l4 = lane & 3;

    // ldmatrix byte addresses (half elements -> *2)
    const uint32_t smb = smem_u32(smh);
    const uint32_t aL = smb +
        (((wm * 32 + (lane & 15)) * GSTR + ((lane >> 4) << 3)) << 1);
    const uint32_t bL = smb + 2 * GTILE_B +
        (((wn * 64 + (((lane >> 4) & 1) << 3) + (lane & 7)) * GSTR +
          (((lane >> 3) & 1) << 3)) << 1);

    load_regs(0);
    store_tile(0);
    __syncthreads();

    const int T = K / 32;
    for (int kt = 0; kt < T; kt++) {
        if (kt + 1 < T) load_regs((kt + 1) * 32);

        const uint32_t ab = aL + (kt & 1) * GTILE_B;
        const uint32_t bb = bL + (kt & 1) * GTILE_B;

        #pragma unroll
        for (int ks = 0; ks < 2; ks++) {
            uint32_t afr[2][4], bfr[16];
            ldsm_x4(afr[0], ab + ks * 32);
            ldsm_x4(afr[1], ab + 16 * GSTR * 2 + ks * 32);
            #pragma unroll
            for (int ntp = 0; ntp < 4; ntp++)
                ldsm_x4(&bfr[ntp * 4], bb + ntp * 16 * GSTR * 2 + ks * 32);
            #pragma unroll
            for (int mt = 0; mt < 2; mt++)
                #pragma unroll
                for (int nt = 0; nt < 8; nt++)
                    mma_f16(acc[mt][nt], afr[mt],
                            &bfr[((nt >> 1) << 2) + ((nt & 1) << 1)]);
        }

        if (kt + 1 < T) {
            store_tile((kt + 1) & 1);
            __syncthreads();
        }
    }

    #pragma unroll
    for (int nt = 0; nt < 8; nt++) {
        int col = bn + wn * 64 + nt * 8 + l4 * 2;
        float b0 = bias[col], b1 = bias[col + 1];
        #pragma unroll
        for (int mt = 0; mt < 2; mt++) {
            int row = bm + wm * 32 + mt * 16 + g4;
            if (row < Mrows) {
                float2 v = make_float2(acc[mt][nt][0] + b0, acc[mt][nt][1] + b1);
                *reinterpret_cast<float2*>(&C[(size_t)row * N + col]) = v;
            }
            if (row + 8 < Mrows) {
                float2 v = make_float2(acc[mt][nt][2] + b0, acc[mt][nt][3] + b1);
                *reinterpret_cast<float2*>(&C[(size_t)(row + 8) * N + col]) = v;
            }
        }
    }
}

// ---------------------------------------------------------------------------
// fp16 tensor-core flash attention, 512 threads (16 warps), warp = 16 Q rows.
// Smem halves: Ks[256][72] roped-K, Vs[256][72] V (row-major, ldmatrix.trans),
// Pb[256][72] (Q staging then per-warp P). Online softmax in log2 domain.
// ---------------------------------------------------------------------------
#define AST   72
#define VS_H  (WSIZE * AST)        /* 18432 */
#define PB_H  (2 * WSIZE * AST)    /* 36864 */
#define ATTN_SMEM_B ((3 * WSIZE * AST) * 2)   /* 110592 bytes */

__global__ void __launch_bounds__(512)
attn_tc_kernel(const float* __restrict__ qkv,
               const float* __restrict__ cosb,
               const float* __restrict__ sinb,
               const int* __restrict__ kvidx,
               float* __restrict__ osc)
{
    extern __shared__ __half shh[];
    __half* Ksm = shh;
    __half* Vsm = shh + VS_H;
    __half* Pbm = shh + PB_H;

    const int w    = blockIdx.x;
    const int h    = blockIdx.y;
    const int tid  = threadIdx.x;
    const int lane = tid & 31;
    const int wid  = tid >> 5;          // 0..15
    const int g4   = lane >> 2;
    const int l4   = lane & 3;
    const int wrow = wid * 16;

    // ---- stage roped K, roped Q (Pb), V as fp16; 2 threads per row ----
    {
        const int row = tid >> 1;
        const int d0  = (tid & 1) * 16;
        const int gi  = w * WSIZE + row;
        const float* qrow = &qkv[(size_t)gi * QKVN + h * HDIM];
        const float* krow = qrow + EMBED;
        const float* vrow = qrow + 2 * EMBED;
        const float* crw  = &cosb[(size_t)gi * HDIM];
        const float* srw  = &sinb[(size_t)gi * HDIM];
        __half* pb = Pbm + row * AST;
        __half* kb = Ksm + row * AST;
        __half* vb = Vsm + row * AST;
        #pragma unroll
        for (int dd = 0; dd < 8; dd++) {
            int d = d0 + dd * 2;
            float2 c  = *reinterpret_cast<const float2*>(crw + d);
            float2 s  = *reinterpret_cast<const float2*>(srw + d);
            float2 qa = *reinterpret_cast<const float2*>(qrow + d);
            float2 qb = *reinterpret_cast<const float2*>(qrow + d + 32);
            float2 ka = *reinterpret_cast<const float2*>(krow + d);
            float2 kb2= *reinterpret_cast<const float2*>(krow + d + 32);
            float2 va = *reinterpret_cast<const float2*>(vrow + d);
            float2 vb2= *reinterpret_cast<const float2*>(vrow + d + 32);
            *reinterpret_cast<uint32_t*>(pb + d)      = packh2(qa.x*c.x - qb.x*s.x, qa.y*c.y - qb.y*s.y);
            *reinterpret_cast<uint32_t*>(pb + d + 32) = packh2(qb.x*c.x + qa.x*s.x, qb.y*c.y + qa.y*s.y);
            *reinterpret_cast<uint32_t*>(kb + d)      = packh2(ka.x*c.x - kb2.x*s.x, ka.y*c.y - kb2.y*s.y);
            *reinterpret_cast<uint32_t*>(kb + d + 32) = packh2(kb2.x*c.x + ka.x*s.x, kb2.y*c.y + ka.y*s.y);
            *reinterpret_cast<uint32_t*>(vb + d)      = packh2(va.x, va.y);
            *reinterpret_cast<uint32_t*>(vb + d + 32) = packh2(vb2.x, vb2.y);
        }
    }
    __syncthreads();

    // ldmatrix byte addresses
    const uint32_t ks_b = smem_u32(Ksm);
    const uint32_t vs_b = smem_u32(Vsm);
    const uint32_t pb_b = smem_u32(Pbm);
    const uint32_t ROWB = AST * 2;   // 144 bytes per smem row
    // A-frags (Q / P) from Pb
    const uint32_t pbA = pb_b +
        (((wrow + (lane & 15)) * AST + ((lane >> 4) << 3)) << 1);
    // B-frags (K) non-trans: rows = key, cols = d
    const uint32_t ksB = ks_b +
        ((((((lane >> 4) & 1) << 3) + (lane & 7)) * AST +
          (((lane >> 3) & 1) << 3)) << 1);
    // B-frags (V) trans: rows = key(k), cols = d(n)
    const uint32_t vsB = vs_b +
        ((((((lane >> 3) & 1) << 3) + (lane & 7)) * AST +
          (((lane >> 4) & 1) << 3)) << 1);

    // ---- Q fragments (4 k16-steps over HDIM) ----
    uint32_t aQ[4][4];
    #pragma unroll
    for (int ks = 0; ks < 4; ks++)
        ldsm_x4(aQ[ks], pbA + ks * 32);
    __syncwarp();

    const float SC = 0.125f * 1.4426950408889634f;   // scale * log2(e)

    float mx[2] = {-1e30f, -1e30f}, lsum[2] = {0.f, 0.f};
    float Oacc[8][4];
    #pragma unroll
    for (int nt = 0; nt < 8; nt++)
        #pragma unroll
        for (int i = 0; i < 4; i++) Oacc[nt][i] = 0.f;

    for (int c = 0; c < 4; c++) {
        const int n0 = c * 64;

        // ---- S = Q K^T chunk [16 x 64] ----
        float Sacc[8][4];
        #pragma unroll
        for (int nt = 0; nt < 8; nt++)
            #pragma unroll
            for (int i = 0; i < 4; i++) Sacc[nt][i] = 0.f;

        #pragma unroll
        for (int ks = 0; ks < 4; ks++) {
            uint32_t bf[16];
            #pragma unroll
            for (int ntp = 0; ntp < 4; ntp++)
                ldsm_x4(&bf[ntp * 4], ksB + (n0 + ntp * 16) * ROWB + ks * 32);
            #pragma unroll
            for (int nt = 0; nt < 8; nt++)
                mma_f16(Sacc[nt], aQ[ks],
                        &bf[((nt >> 1) << 2) + ((nt & 1) << 1)]);
        }

        // ---- online softmax (log2 domain) ----
        #pragma unroll
        for (int hf = 0; hf < 2; hf++) {
            float rm = -1e30f;
            #pragma unroll
            for (int nt = 0; nt < 8; nt++) {
                rm = fmaxf(rm, Sacc[nt][2*hf]);
                rm = fmaxf(rm, Sacc[nt][2*hf+1]);
            }
            rm = fmaxf(rm, __shfl_xor_sync(0xffffffffu, rm, 1));
            rm = fmaxf(rm, __shfl_xor_sync(0xffffffffu, rm, 2));
            float nmx = fmaxf(mx[hf], rm * SC);
            float corr = ex2f(mx[hf] - nmx);
            mx[hf] = nmx;

            float ps = 0.f;
            #pragma unroll
            for (int nt = 0; nt < 8; nt++) {
                float p0 = ex2f(fmaf(Sacc[nt][2*hf],   SC, -nmx));
                float p1 = ex2f(fmaf(Sacc[nt][2*hf+1], SC, -nmx));
                ps += p0 + p1;
                Sacc[nt][2*hf]   = p0;
                Sacc[nt][2*hf+1] = p1;
            }
            ps += __shfl_xor_sync(0xffffffffu, ps, 1);
            ps += __shfl_xor_sync(0xffffffffu, ps, 2);
            lsum[hf] = lsum[hf] * corr + ps;

            #pragma unroll
            for (int nt = 0; nt < 8; nt++) {
                Oacc[nt][2*hf]   *= corr;
                Oacc[nt][2*hf+1] *= corr;
            }
        }

        // ---- write P (fp16) to own Pb rows ----
        {
            int r0 = wrow + g4;
            __half* p0r = Pbm + r0 * AST;
            __half* p1r = Pbm + (r0 + 8) * AST;
            #pragma unroll
            for (int nt = 0; nt < 8; nt++) {
                int col = nt * 8 + 2 * l4;
                *reinterpret_cast<uint32_t*>(p0r + col) = packh2(Sacc[nt][0], Sacc[nt][1]);
                *reinterpret_cast<uint32_t*>(p1r + col) = packh2(Sacc[nt][2], Sacc[nt][3]);
            }
        }
        __syncwarp();

        // ---- O += P V chunk ----
        #pragma unroll
        for (int ks = 0; ks < 4; ks++) {
            uint32_t aP[4], bv[16];
            ldsm_x4(aP, pbA + ks * 32);
            #pragma unroll
            for (int ntp = 0; ntp < 4; ntp++)
                ldsm_x4_t(&bv[ntp * 4], vsB + (n0 + ks * 16) * ROWB + ntp * 32);
            #pragma unroll
            for (int nt = 0; nt < 8; nt++)
                mma_f16(Oacc[nt], aP,
                        &bv[((nt >> 1) << 2) + ((nt & 1) << 1)]);
        }
        __syncwarp();
    }

    // ---- epilogue: normalize + scattered store ----
    {
        int r0 = wrow + g4;
        float inv0 = 1.f / lsum[0];
        float inv1 = 1.f / lsum[1];
        int o0 = kvidx[w * WSIZE + r0];
        int o1 = kvidx[w * WSIZE + r0 + 8];
        float* base0 = &osc[(size_t)o0 * EMBED + h * HDIM];
        float* base1 = &osc[(size_t)o1 * EMBED + h * HDIM];
        #pragma unroll
        for (int nt = 0; nt < 8; nt++) {
            int col = nt * 8 + 2 * l4;
            float2 v0 = make_float2(Oacc[nt][0] * inv0, Oacc[nt][1] * inv0);
            float2 v1 = make_float2(Oacc[nt][2] * inv1, Oacc[nt][3] * inv1);
            *reinterpret_cast<float2*>(&base0[col]) = v0;
            *reinterpret_cast<float2*>(&base1[col]) = v1;
        }
    }
}

// ---------------------------------------------------------------------------
extern "C" void kernel_launch(void* const* d_in, const int* in_sizes, int n_in,
                              void* d_out, int out_size)
{
    const float* x      = (const float*)d_in[0];
    const float* qkv_w  = (const float*)d_in[1];
    const float* qkv_b  = (const float*)d_in[2];
    const float* proj_w = (const float*)d_in[3];
    const float* proj_b = (const float*)d_in[4];
    const float* rope_c = (const float*)d_in[6];
    const float* rope_s = (const float*)d_in[7];
    const int*   kvi    = (const int*)d_in[8];
    float*       out    = (float*)d_out;

    float *qkv_buf = nullptr, *osc_buf = nullptr;
    cudaGetSymbolAddress((void**)&qkv_buf, g_qkv);
    cudaGetSymbolAddress((void**)&osc_buf, g_osc);

    const int gemm_smem = 4 * GTILE_B;   // 40960 B
    cudaFuncSetAttribute(h16_gemm_kernel,
                         cudaFuncAttributeMaxDynamicSharedMemorySize, gemm_smem);

    // 1) QKV GEMM with fused row gather
    {
        dim3 grid(QKVN / 128, MTOT / 128);
        h16_gemm_kernel<<<grid, 256, gemm_smem>>>(x, qkv_w, qkv_b, qkv_buf, kvi,
                                                  MTOT, QKVN, EMBED, LTOT);
    }

    // 2) fp16 tensor-core flash attention (RoPE + scatter fused)
    {
        cudaFuncSetAttribute(attn_tc_kernel,
                             cudaFuncAttributeMaxDynamicSharedMemorySize, ATTN_SMEM_B);
        dim3 grid(NWIN, NHEADS);
        attn_tc_kernel<<<grid, 512, ATTN_SMEM_B>>>(qkv_buf, rope_c, rope_s, kvi, osc_buf);
    }

    // 3) Output projection
    {
        dim3 grid(EMBED / 128, (LTOT + 127) / 128);
        h16_gemm_kernel<<<grid, 256, gemm_smem>>>(osc_buf, proj_w, proj_b, out, nullptr,
                                                  LTOT, EMBED, EMBED, MTOT);
    }
}

// round 9
// speedup vs baseline: 2.1761x; 2.1761x over previous
#include <cuda_runtime.h>
#include <cuda_fp16.h>
#include <cstdint>
#include <cstddef>

#define EMBED    1024
#define NHEADS   16
#define HDIM     64
#define WSIZE    256
#define NWIN     64
#define MTOT     (NWIN*WSIZE)     /* 16384 */
#define LTOT     (MTOT-1)         /* 16383 */
#define QKVN     (3*EMBED)        /* 3072  */

// Scratch (allocation-free rule: __device__ globals)
__device__ __half g_xh[(size_t)MTOT * EMBED];    // x in fp16, padding row zeroed
__device__ __half g_wqkv[(size_t)QKVN * EMBED];  // qkv_w fp16
__device__ __half g_wproj[(size_t)EMBED * EMBED];// proj_w fp16
__device__ __half g_qkvh[(size_t)MTOT * QKVN];   // gathered-order qkv fp16
__device__ __half g_osch[(size_t)MTOT * EMBED];  // scattered attention out fp16

__device__ __forceinline__ float ex2f(float x) {
    float y;
    asm("ex2.approx.f32 %0, %1;" : "=f"(y) : "f"(x));
    return y;
}
__device__ __forceinline__ uint32_t packh2(float lo, float hi) {
    __half2 h = __floats2half2_rn(lo, hi);
    return *reinterpret_cast<uint32_t*>(&h);
}
__device__ __forceinline__ void mma_f16(float* c, const uint32_t* a, const uint32_t* b) {
    asm volatile(
        "mma.sync.aligned.m16n8k16.row.col.f32.f16.f16.f32 "
        "{%0,%1,%2,%3}, {%4,%5,%6,%7}, {%8,%9}, {%0,%1,%2,%3};"
        : "+f"(c[0]), "+f"(c[1]), "+f"(c[2]), "+f"(c[3])
        : "r"(a[0]), "r"(a[1]), "r"(a[2]), "r"(a[3]), "r"(b[0]), "r"(b[1]));
}
__device__ __forceinline__ void ldsm_x4(uint32_t* r, uint32_t addr) {
    asm volatile("ldmatrix.sync.aligned.m8n8.x4.shared.b16 {%0,%1,%2,%3}, [%4];"
                 : "=r"(r[0]), "=r"(r[1]), "=r"(r[2]), "=r"(r[3]) : "r"(addr));
}
__device__ __forceinline__ void ldsm_x4_t(uint32_t* r, uint32_t addr) {
    asm volatile("ldmatrix.sync.aligned.m8n8.x4.trans.shared.b16 {%0,%1,%2,%3}, [%4];"
                 : "=r"(r[0]), "=r"(r[1]), "=r"(r[2]), "=r"(r[3]) : "r"(addr));
}
__device__ __forceinline__ uint32_t smem_u32(const void* p) {
    uint32_t a;
    asm("{ .reg .u64 t; cvta.to.shared.u64 t, %1; cvt.u32.u64 %0, t; }"
        : "=r"(a) : "l"(p));
    return a;
}

// ---------------------------------------------------------------------------
// fp32 -> fp16 conversion, zero-fills [n_src, n_tot)
// ---------------------------------------------------------------------------
__global__ void cvt_kernel(const float* __restrict__ src, __half* __restrict__ dst,
                           int n_src, int n_tot)
{
    int i = (blockIdx.x * blockDim.x + threadIdx.x) << 2;
    if (i >= n_tot) return;
    uint2 u;
    if (i < n_src) {
        float4 v = *reinterpret_cast<const float4*>(src + i);
        u.x = packh2(v.x, v.y);
        u.y = packh2(v.z, v.w);
    } else {
        u = make_uint2(0u, 0u);
    }
    *reinterpret_cast<uint2*>(dst + i) = u;
}

// ---------------------------------------------------------------------------
// fp16 tensor-core GEMM (fp32 accum), fp16 operands in gmem:
//   C[m][n] = sum_k A[row(m)][k] * B[n][k] + bias[n]
//   BM=BN=128, BK=32(halves), 256 threads (8 warps, 4x2), warp tile 32x64,
//   mma.m16n8k16, smem tiles 128x40 halves.
//   Output: Ch (fp16) if non-null else Cf (fp32).
// ---------------------------------------------------------------------------
#define GSTR    40                 /* halves per smem row  */
#define GTILE_H (128 * GSTR)       /* 5120 halves per tile */
#define GTILE_B (GTILE_H * 2)      /* 10240 bytes          */

__global__ void __launch_bounds__(256, 2)
h16_gemm_kernel(const __half* __restrict__ A,
                const __half* __restrict__ B,
                const float* __restrict__ bias,
                float* __restrict__ Cf,
                __half* __restrict__ Ch,
                const int* __restrict__ gidx,
                int Mrows, int N, int K)
{
    extern __shared__ __half smh[];
    __half* As = smh;                  // [2][128][40]
    __half* Bs = smh + 2 * GTILE_H;    // [2][128][40]
    __shared__ int arow[128];

    const int tid  = threadIdx.x;
    const int lane = tid & 31;
    const int wid  = tid >> 5;
    const int wm   = wid & 3;
    const int wn   = wid >> 2;
    const int bm   = blockIdx.y * 128;
    const int bn   = blockIdx.x * 128;

    if (tid < 128) {
        int m = bm + tid;
        int r;
        if (m < Mrows) r = gidx ? gidx[m] : m;
        else           r = 0;             // clamped; epilogue masks stores
        arow[tid] = r;
    }
    __syncthreads();

    // copy mapping: 4 threads/row, 8 halves (16B) each; 64 rows per pass, 2 passes
    const int crow = tid >> 2;            // 0..63
    const int ckq  = (tid & 3) << 3;      // 0,8,16,24 halves

    uint4 ra[2], rb[2];

    auto load_regs = [&](int k0) {
        #pragma unroll
        for (int i = 0; i < 2; i++) {
            int row = crow + i * 64;
            ra[i] = *reinterpret_cast<const uint4*>(&A[(size_t)arow[row] * K + k0 + ckq]);
            rb[i] = *reinterpret_cast<const uint4*>(&B[(size_t)(bn + row) * K + k0 + ckq]);
        }
    };

    auto store_tile = [&](int buf) {
        #pragma unroll
        for (int i = 0; i < 2; i++) {
            int row = crow + i * 64;
            *reinterpret_cast<uint4*>(&As[buf * GTILE_H + row * GSTR + ckq]) = ra[i];
            *reinterpret_cast<uint4*>(&Bs[buf * GTILE_H + row * GSTR + ckq]) = rb[i];
        }
    };

    float acc[2][8][4];
    #pragma unroll
    for (int mt = 0; mt < 2; mt++)
        #pragma unroll
        for (int nt = 0; nt < 8; nt++)
            #pragma unroll
            for (int i = 0; i < 4; i++) acc[mt][nt][i] = 0.f;

    const int g4 = lane >> 2;
    const int l4 = lane & 3;

    // ldmatrix byte addresses (half elements -> *2)
    const uint32_t smb = smem_u32(smh);
    const uint32_t aL = smb +
        (((wm * 32 + (lane & 15)) * GSTR + ((lane >> 4) << 3)) << 1);
    const uint32_t bL = smb + 2 * GTILE_B +
        (((wn * 64 + (((lane >> 4) & 1) << 3) + (lane & 7)) * GSTR +
          (((lane >> 3) & 1) << 3)) << 1);

    load_regs(0);
    store_tile(0);
    __syncthreads();

    const int T = K / 32;
    for (int kt = 0; kt < T; kt++) {
        if (kt + 1 < T) load_regs((kt + 1) * 32);

        const uint32_t ab = aL + (kt & 1) * GTILE_B;
        const uint32_t bb = bL + (kt & 1) * GTILE_B;

        #pragma unroll
        for (int ks = 0; ks < 2; ks++) {
            uint32_t afr[2][4], bfr[16];
            ldsm_x4(afr[0], ab + ks * 32);
            ldsm_x4(afr[1], ab + 16 * GSTR * 2 + ks * 32);
            #pragma unroll
            for (int ntp = 0; ntp < 4; ntp++)
                ldsm_x4(&bfr[ntp * 4], bb + ntp * 16 * GSTR * 2 + ks * 32);
            #pragma unroll
            for (int mt = 0; mt < 2; mt++)
                #pragma unroll
                for (int nt = 0; nt < 8; nt++)
                    mma_f16(acc[mt][nt], afr[mt],
                            &bfr[((nt >> 1) << 2) + ((nt & 1) << 1)]);
        }

        if (kt + 1 < T) {
            store_tile((kt + 1) & 1);
            __syncthreads();
        }
    }

    #pragma unroll
    for (int nt = 0; nt < 8; nt++) {
        int col = bn + wn * 64 + nt * 8 + l4 * 2;
        float b0 = bias[col], b1 = bias[col + 1];
        #pragma unroll
        for (int mt = 0; mt < 2; mt++) {
            int row = bm + wm * 32 + mt * 16 + g4;
            if (row < Mrows) {
                if (Ch)
                    *reinterpret_cast<uint32_t*>(&Ch[(size_t)row * N + col]) =
                        packh2(acc[mt][nt][0] + b0, acc[mt][nt][1] + b1);
                else {
                    float2 v = make_float2(acc[mt][nt][0] + b0, acc[mt][nt][1] + b1);
                    *reinterpret_cast<float2*>(&Cf[(size_t)row * N + col]) = v;
                }
            }
            if (row + 8 < Mrows) {
                if (Ch)
                    *reinterpret_cast<uint32_t*>(&Ch[(size_t)(row + 8) * N + col]) =
                        packh2(acc[mt][nt][2] + b0, acc[mt][nt][3] + b1);
                else {
                    float2 v = make_float2(acc[mt][nt][2] + b0, acc[mt][nt][3] + b1);
                    *reinterpret_cast<float2*>(&Cf[(size_t)(row + 8) * N + col]) = v;
                }
            }
        }
    }
}

// ---------------------------------------------------------------------------
// fp16 tensor-core flash attention, 512 threads (16 warps), warp = 16 Q rows.
// qkv input fp16; osc output fp16 (scatter). Online softmax in log2 domain.
// ---------------------------------------------------------------------------
#define AST   72
#define VS_H  (WSIZE * AST)        /* 18432 */
#define PB_H  (2 * WSIZE * AST)    /* 36864 */
#define ATTN_SMEM_B ((3 * WSIZE * AST) * 2)   /* 110592 bytes */

__global__ void __launch_bounds__(512)
attn_tc_kernel(const __half* __restrict__ qkv,
               const float* __restrict__ cosb,
               const float* __restrict__ sinb,
               const int* __restrict__ kvidx,
               __half* __restrict__ osc)
{
    extern __shared__ __half shh[];
    __half* Ksm = shh;
    __half* Vsm = shh + VS_H;
    __half* Pbm = shh + PB_H;

    const int w    = blockIdx.x;
    const int h    = blockIdx.y;
    const int tid  = threadIdx.x;
    const int lane = tid & 31;
    const int wid  = tid >> 5;          // 0..15
    const int g4   = lane >> 2;
    const int l4   = lane & 3;
    const int wrow = wid * 16;

    // ---- stage roped K, roped Q (Pb), V as fp16; 2 threads per row ----
    {
        const int row = tid >> 1;
        const int d0  = (tid & 1) * 16;
        const int gi  = w * WSIZE + row;
        const __half* qrow = &qkv[(size_t)gi * QKVN + h * HDIM];
        const __half* krow = qrow + EMBED;
        const __half* vrow = qrow + 2 * EMBED;
        const float* crw  = &cosb[(size_t)gi * HDIM];
        const float* srw  = &sinb[(size_t)gi * HDIM];
        __half* pb = Pbm + row * AST;
        __half* kb = Ksm + row * AST;
        __half* vb = Vsm + row * AST;
        #pragma unroll
        for (int dd = 0; dd < 8; dd++) {
            int d = d0 + dd * 2;
            float2 c   = *reinterpret_cast<const float2*>(crw + d);
            float2 s   = *reinterpret_cast<const float2*>(srw + d);
            float2 qa  = __half22float2(*reinterpret_cast<const __half2*>(qrow + d));
            float2 qb  = __half22float2(*reinterpret_cast<const __half2*>(qrow + d + 32));
            float2 ka  = __half22float2(*reinterpret_cast<const __half2*>(krow + d));
            float2 kb2 = __half22float2(*reinterpret_cast<const __half2*>(krow + d + 32));
            *reinterpret_cast<uint32_t*>(pb + d)      = packh2(qa.x*c.x - qb.x*s.x, qa.y*c.y - qb.y*s.y);
            *reinterpret_cast<uint32_t*>(pb + d + 32) = packh2(qb.x*c.x + qa.x*s.x, qb.y*c.y + qa.y*s.y);
            *reinterpret_cast<uint32_t*>(kb + d)      = packh2(ka.x*c.x - kb2.x*s.x, ka.y*c.y - kb2.y*s.y);
            *reinterpret_cast<uint32_t*>(kb + d + 32) = packh2(kb2.x*c.x + ka.x*s.x, kb2.y*c.y + ka.y*s.y);
            *reinterpret_cast<uint32_t*>(vb + d)      =
                *reinterpret_cast<const uint32_t*>(vrow + d);
            *reinterpret_cast<uint32_t*>(vb + d + 32) =
                *reinterpret_cast<const uint32_t*>(vrow + d + 32);
        }
    }
    __syncthreads();

    // ldmatrix byte addresses
    const uint32_t ks_b = smem_u32(Ksm);
    const uint32_t vs_b = smem_u32(Vsm);
    const uint32_t pb_b = smem_u32(Pbm);
    const uint32_t ROWB = AST * 2;   // 144 bytes per smem row
    const uint32_t pbA = pb_b +
        (((wrow + (lane & 15)) * AST + ((lane >> 4) << 3)) << 1);
    const uint32_t ksB = ks_b +
        ((((((lane >> 4) & 1) << 3) + (lane & 7)) * AST +
          (((lane >> 3) & 1) << 3)) << 1);
    const uint32_t vsB = vs_b +
        ((((((lane >> 3) & 1) << 3) + (lane & 7)) * AST +
          (((lane >> 4) & 1) << 3)) << 1);

    // ---- Q fragments (4 k16-steps over HDIM) ----
    uint32_t aQ[4][4];
    #pragma unroll
    for (int ks = 0; ks < 4; ks++)
        ldsm_x4(aQ[ks], pbA + ks * 32);
    __syncwarp();

    const float SC = 0.125f * 1.4426950408889634f;   // scale * log2(e)

    float mx[2] = {-1e30f, -1e30f}, lsum[2] = {0.f, 0.f};
    float Oacc[8][4];
    #pragma unroll
    for (int nt = 0; nt < 8; nt++)
        #pragma unroll
        for (int i = 0; i < 4; i++) Oacc[nt][i] = 0.f;

    for (int c = 0; c < 4; c++) {
        const int n0 = c * 64;

        // ---- S = Q K^T chunk [16 x 64] ----
        float Sacc[8][4];
        #pragma unroll
        for (int nt = 0; nt < 8; nt++)
            #pragma unroll
            for (int i = 0; i < 4; i++) Sacc[nt][i] = 0.f;

        #pragma unroll
        for (int ks = 0; ks < 4; ks++) {
            uint32_t bf[16];
            #pragma unroll
            for (int ntp = 0; ntp < 4; ntp++)
                ldsm_x4(&bf[ntp * 4], ksB + (n0 + ntp * 16) * ROWB + ks * 32);
            #pragma unroll
            for (int nt = 0; nt < 8; nt++)
                mma_f16(Sacc[nt], aQ[ks],
                        &bf[((nt >> 1) << 2) + ((nt & 1) << 1)]);
        }

        // ---- online softmax (log2 domain) ----
        #pragma unroll
        for (int hf = 0; hf < 2; hf++) {
            float rm = -1e30f;
            #pragma unroll
            for (int nt = 0; nt < 8; nt++) {
                rm = fmaxf(rm, Sacc[nt][2*hf]);
                rm = fmaxf(rm, Sacc[nt][2*hf+1]);
            }
            rm = fmaxf(rm, __shfl_xor_sync(0xffffffffu, rm, 1));
            rm = fmaxf(rm, __shfl_xor_sync(0xffffffffu, rm, 2));
            float nmx = fmaxf(mx[hf], rm * SC);
            float corr = ex2f(mx[hf] - nmx);
            mx[hf] = nmx;

            float ps = 0.f;
            #pragma unroll
            for (int nt = 0; nt < 8; nt++) {
                float p0 = ex2f(fmaf(Sacc[nt][2*hf],   SC, -nmx));
                float p1 = ex2f(fmaf(Sacc[nt][2*hf+1], SC, -nmx));
                ps += p0 + p1;
                Sacc[nt][2*hf]   = p0;
                Sacc[nt][2*hf+1] = p1;
            }
            ps += __shfl_xor_sync(0xffffffffu, ps, 1);
            ps += __shfl_xor_sync(0xffffffffu, ps, 2);
            lsum[hf] = lsum[hf] * corr + ps;

            #pragma unroll
            for (int nt = 0; nt < 8; nt++) {
                Oacc[nt][2*hf]   *= corr;
                Oacc[nt][2*hf+1] *= corr;
            }
        }

        // ---- write P (fp16) to own Pb rows ----
        {
            int r0 = wrow + g4;
            __half* p0r = Pbm + r0 * AST;
            __half* p1r = Pbm + (r0 + 8) * AST;
            #pragma unroll
            for (int nt = 0; nt < 8; nt++) {
                int col = nt * 8 + 2 * l4;
                *reinterpret_cast<uint32_t*>(p0r + col) = packh2(Sacc[nt][0], Sacc[nt][1]);
                *reinterpret_cast<uint32_t*>(p1r + col) = packh2(Sacc[nt][2], Sacc[nt][3]);
            }
        }
        __syncwarp();

        // ---- O += P V chunk ----
        #pragma unroll
        for (int ks = 0; ks < 4; ks++) {
            uint32_t aP[4], bv[16];
            ldsm_x4(aP, pbA + ks * 32);
            #pragma unroll
            for (int ntp = 0; ntp < 4; ntp++)
                ldsm_x4_t(&bv[ntp * 4], vsB + (n0 + ks * 16) * ROWB + ntp * 32);
            #pragma unroll
            for (int nt = 0; nt < 8; nt++)
                mma_f16(Oacc[nt], aP,
                        &bv[((nt >> 1) << 2) + ((nt & 1) << 1)]);
        }
        __syncwarp();
    }

    // ---- epilogue: normalize + scattered fp16 store ----
    {
        int r0 = wrow + g4;
        float inv0 = 1.f / lsum[0];
        float inv1 = 1.f / lsum[1];
        int o0 = kvidx[w * WSIZE + r0];
        int o1 = kvidx[w * WSIZE + r0 + 8];
        __half* base0 = &osc[(size_t)o0 * EMBED + h * HDIM];
        __half* base1 = &osc[(size_t)o1 * EMBED + h * HDIM];
        #pragma unroll
        for (int nt = 0; nt < 8; nt++) {
            int col = nt * 8 + 2 * l4;
            *reinterpret_cast<uint32_t*>(base0 + col) =
                packh2(Oacc[nt][0] * inv0, Oacc[nt][1] * inv0);
            *reinterpret_cast<uint32_t*>(base1 + col) =
                packh2(Oacc[nt][2] * inv1, Oacc[nt][3] * inv1);
        }
    }
}

// ---------------------------------------------------------------------------
extern "C" void kernel_launch(void* const* d_in, const int* in_sizes, int n_in,
                              void* d_out, int out_size)
{
    const float* x      = (const float*)d_in[0];
    const float* qkv_w  = (const float*)d_in[1];
    const float* qkv_b  = (const float*)d_in[2];
    const float* proj_w = (const float*)d_in[3];
    const float* proj_b = (const float*)d_in[4];
    const float* rope_c = (const float*)d_in[6];
    const float* rope_s = (const float*)d_in[7];
    const int*   kvi    = (const int*)d_in[8];
    float*       out    = (float*)d_out;

    __half *xh, *wqkv, *wproj, *qkvh, *osch;
    cudaGetSymbolAddress((void**)&xh,    g_xh);
    cudaGetSymbolAddress((void**)&wqkv,  g_wqkv);
    cudaGetSymbolAddress((void**)&wproj, g_wproj);
    cudaGetSymbolAddress((void**)&qkvh,  g_qkvh);
    cudaGetSymbolAddress((void**)&osch,  g_osch);

    // 0) fp32 -> fp16 conversions (x padded with zero row)
    {
        int nx_src = LTOT * EMBED, nx_tot = MTOT * EMBED;
        cvt_kernel<<<(nx_tot / 4 + 255) / 256, 256>>>(x, xh, nx_src, nx_tot);
        int nw = QKVN * EMBED;
        cvt_kernel<<<(nw / 4 + 255) / 256, 256>>>(qkv_w, wqkv, nw, nw);
        int np = EMBED * EMBED;
        cvt_kernel<<<(np / 4 + 255) / 256, 256>>>(proj_w, wproj, np, np);
    }

    const int gemm_smem = 4 * GTILE_B;   // 40960 B
    cudaFuncSetAttribute(h16_gemm_kernel,
                         cudaFuncAttributeMaxDynamicSharedMemorySize, gemm_smem);

    // 1) QKV GEMM with fused row gather (fp16 in, fp16 out)
    {
        dim3 grid(QKVN / 128, MTOT / 128);
        h16_gemm_kernel<<<grid, 256, gemm_smem>>>(xh, wqkv, qkv_b, nullptr, qkvh,
                                                  kvi, MTOT, QKVN, EMBED);
    }

    // 2) fp16 tensor-core flash attention (RoPE + scatter fused)
    {
        cudaFuncSetAttribute(attn_tc_kernel,
                             cudaFuncAttributeMaxDynamicSharedMemorySize, ATTN_SMEM_B);
        dim3 grid(NWIN, NHEADS);
        attn_tc_kernel<<<grid, 512, ATTN_SMEM_B>>>(qkvh, rope_c, rope_s, kvi, osch);
    }

    // 3) Output projection (fp16 in, fp32 out)
    {
        dim3 grid(EMBED / 128, (LTOT + 127) / 128);
        h16_gemm_kernel<<<grid, 256, gemm_smem>>>(osch, wproj, proj_b, out, nullptr,
                                                  nullptr, LTOT, EMBED, EMBED);
    }
}